// round 10
// baseline (speedup 1.0000x reference)
#include <cuda_runtime.h>
#include <cstdint>

// Problem constants
#define BB      8
#define CC      512
#define NN      1024      // H*W
#define NH      8
#define GG      32        // groups
#define CPG     16        // channels per group
#define EPSV    1e-5f

// Scratch (device globals — no allocation allowed)
__device__ float g_hn  [(size_t)BB * CC * NN];          // GN1 output (tf32-rounded)
__device__ float g_qkv [(size_t)BB * 3 * CC * NN];      // qkv (tf32-rounded)
__device__ float g_attn[(size_t)BB * CC * NN];          // attention out (tf32-rounded)
__device__ float g_proj[(size_t)BB * CC * NN];          // proj out (raw fp32)
__device__ float g_wq  [(size_t)3 * CC * CC];           // rounded w_qkv
__device__ float g_wp  [(size_t)CC * CC];               // rounded w_proj

// ===========================================================================
// helpers
// ===========================================================================
__device__ __forceinline__ float totf(float x) {
    uint32_t r;
    asm("cvt.rna.tf32.f32 %0, %1;" : "=r"(r) : "f"(x));
    return __uint_as_float(r);
}

__device__ __forceinline__ void mma_tf32(float* c, const uint32_t* a, const uint32_t* b) {
    asm volatile(
        "mma.sync.aligned.m16n8k8.row.col.f32.tf32.tf32.f32 "
        "{%0,%1,%2,%3}, {%4,%5,%6,%7}, {%8,%9}, {%0,%1,%2,%3};"
        : "+f"(c[0]), "+f"(c[1]), "+f"(c[2]), "+f"(c[3])
        : "r"(a[0]), "r"(a[1]), "r"(a[2]), "r"(a[3]), "r"(b[0]), "r"(b[1]));
}

__device__ __forceinline__ uint32_t sptr(const void* p) {
    return (uint32_t)__cvta_generic_to_shared(p);
}
__device__ __forceinline__ void cp16(uint32_t dst, const void* src) {
    asm volatile("cp.async.cg.shared.global [%0], [%1], 16;" :: "r"(dst), "l"(src));
}
__device__ __forceinline__ void cp4(uint32_t dst, const void* src) {
    asm volatile("cp.async.ca.shared.global [%0], [%1], 4;" :: "r"(dst), "l"(src));
}
#define CP_COMMIT() asm volatile("cp.async.commit_group;" ::: "memory")
#define CP_WAIT2()  asm volatile("cp.async.wait_group 2;" ::: "memory")
#define CP_WAIT0()  asm volatile("cp.async.wait_group 0;" ::: "memory")

// ===========================================================================
// Weight pre-rounding (w_qkv -> g_wq, w_proj -> g_wp)
// ===========================================================================
__global__ void k_roundw(const float* __restrict__ wq, const float* __restrict__ wp) {
    int i = blockIdx.x * 256 + threadIdx.x;
    const int NQ = 3 * CC * CC;   // 786432
    if (i < NQ) g_wq[i] = totf(wq[i]);
    else {
        int j = i - NQ;
        g_wp[j] = totf(wp[j]);
    }
}

// ===========================================================================
// Generic tf32 mma.sync GEMM with 4-stage cp.async pipeline.
//   D[c (128)][r (128)] = sum_k A[c][k] * B[k][r]
//   A: direct (src[c][k], pre-rounded), B: transpose (src[k][r], pre-rounded)
// 8 warps = 2 (M) x 4 (N); warp tile 64x32; mma m16n8k8; BK=16.
// dynamic smem: 4 stages x (As 128x20 + Bs 128x20) floats = 81920 B
// ===========================================================================
#define SPAD 20
#define STG_F (128 * SPAD)        // floats per operand-stage

template<bool RND>
__device__ __forceinline__ void gemm_core(
    const float* __restrict__ Asrc, int ldA,
    const float* __restrict__ Bsrc, int ldB,
    float* __restrict__ Out, const float* __restrict__ bias, int K)
{
    extern __shared__ float smem[];
    float* As = smem;                 // [4][STG_F]
    float* Bs = smem + 4 * STG_F;     // [4][STG_F]

    const int tid = threadIdx.x;
    const int wid = tid >> 5, lane = tid & 31;
    const int wm = wid & 1, wn = wid >> 1;
    const int grp = lane >> 2, tig = lane & 3;

    const uint32_t sA = sptr(As);
    const uint32_t sB = sptr(Bs);

    // A issue: 512 16B chunks, 2 per thread
    const int a_row0 = tid >> 2, a_kq = (tid & 3) * 4;
    const int a_row1 = (tid + 256) >> 2;
    // B issue (transpose): 2 tasks per thread, 4 x 4B each
    const int b_q0 = (wid * 2) & 3, b_r0 = ((wid * 2) >> 2) * 32 + lane;
    const int b_q1 = (wid * 2 + 1) & 3, b_r1 = ((wid * 2 + 1) >> 2) * 32 + lane;

    auto issue = [&](int it, int stage) {
        uint32_t da = sA + (uint32_t)(stage * STG_F) * 4;
        cp16(da + (a_row0 * SPAD + a_kq) * 4, Asrc + (size_t)a_row0 * ldA + it * 16 + a_kq);
        cp16(da + (a_row1 * SPAD + a_kq) * 4, Asrc + (size_t)a_row1 * ldA + it * 16 + a_kq);
        uint32_t db = sB + (uint32_t)(stage * STG_F) * 4;
        #pragma unroll
        for (int i = 0; i < 4; i++)
            cp4(db + (b_r0 * SPAD + b_q0 * 4 + i) * 4,
                Bsrc + (size_t)(it * 16 + b_q0 * 4 + i) * ldB + b_r0);
        #pragma unroll
        for (int i = 0; i < 4; i++)
            cp4(db + (b_r1 * SPAD + b_q1 * 4 + i) * 4,
                Bsrc + (size_t)(it * 16 + b_q1 * 4 + i) * ldB + b_r1);
    };

    float acc[4][4][4];
    #pragma unroll
    for (int i = 0; i < 4; i++)
        #pragma unroll
        for (int j = 0; j < 4; j++)
            #pragma unroll
            for (int e = 0; e < 4; e++) acc[i][j][e] = 0.f;

    const int nK = K >> 4;    // >= 32 here

    // prologue: 3 stages in flight
    issue(0, 0); CP_COMMIT();
    issue(1, 1); CP_COMMIT();
    issue(2, 2); CP_COMMIT();

    for (int it = 0; it < nK; it++) {
        CP_WAIT2();
        __syncthreads();

        if (it + 3 < nK) issue(it + 3, (it + 3) & 3);
        CP_COMMIT();    // real or empty — keeps group counting uniform

        const float* Ab = As + (it & 3) * STG_F;
        const float* Bb = Bs + (it & 3) * STG_F;
        #pragma unroll
        for (int kk = 0; kk < 2; kk++) {
            uint32_t a[4][4];
            #pragma unroll
            for (int i = 0; i < 4; i++) {
                int c = wm * 64 + i * 16 + grp;
                int k = kk * 8 + tig;
                a[i][0] = __float_as_uint(Ab[c * SPAD + k]);
                a[i][1] = __float_as_uint(Ab[(c + 8) * SPAD + k]);
                a[i][2] = __float_as_uint(Ab[c * SPAD + k + 4]);
                a[i][3] = __float_as_uint(Ab[(c + 8) * SPAD + k + 4]);
            }
            uint32_t b[4][2];
            #pragma unroll
            for (int j = 0; j < 4; j++) {
                int r = wn * 32 + j * 8 + grp;
                int k = kk * 8 + tig;
                b[j][0] = __float_as_uint(Bb[r * SPAD + k]);
                b[j][1] = __float_as_uint(Bb[r * SPAD + k + 4]);
            }
            #pragma unroll
            for (int i = 0; i < 4; i++)
                #pragma unroll
                for (int j = 0; j < 4; j++)
                    mma_tf32(acc[i][j], a[i], b[j]);
        }
    }

    #pragma unroll
    for (int i = 0; i < 4; i++) {
        int c = wm * 64 + i * 16 + grp;
        float bv0 = bias ? bias[c] : 0.f;
        float bv1 = bias ? bias[c + 8] : 0.f;
        #pragma unroll
        for (int j = 0; j < 4; j++) {
            int r = wn * 32 + j * 8 + tig * 2;
            float2 v0, v1;
            if (RND) {
                v0 = { totf(acc[i][j][0] + bv0), totf(acc[i][j][1] + bv0) };
                v1 = { totf(acc[i][j][2] + bv1), totf(acc[i][j][3] + bv1) };
            } else {
                v0 = { acc[i][j][0] + bv0, acc[i][j][1] + bv0 };
                v1 = { acc[i][j][2] + bv1, acc[i][j][3] + bv1 };
            }
            *(float2*)&Out[(size_t)c * NN + r] = v0;
            *(float2*)&Out[(size_t)(c + 8) * NN + r] = v1;
        }
    }
}

#define GEMM_SMEM (8 * STG_F * (int)sizeof(float))   // 81920 B

__global__ void __launch_bounds__(256, 2) k_qkv(const float* __restrict__ bias) {
    int n0 = blockIdx.x * 128, m0 = blockIdx.y * 128, b = blockIdx.z;
    gemm_core<true>(g_wq + (size_t)m0 * CC, CC,
                    g_hn + (size_t)b * CC * NN + n0, NN,
                    g_qkv + (size_t)b * 3 * CC * NN + (size_t)m0 * NN + n0,
                    bias + m0, CC);
}

__global__ void __launch_bounds__(256, 2) k_proj(const float* __restrict__ bias) {
    int n0 = blockIdx.x * 128, m0 = blockIdx.y * 128, b = blockIdx.z;
    gemm_core<false>(g_wp + (size_t)m0 * CC, CC,
                     g_attn + (size_t)b * CC * NN + n0, NN,
                     g_proj + (size_t)b * CC * NN + (size_t)m0 * NN + n0,
                     bias + m0, CC);
}

// ===========================================================================
// Flash attention (tf32 mma.sync, fused softmax).
// One block = one (bh, 128-query tile). 8 warps; warp w owns t-rows
// [w*16, w*16+16). Q fragments hoisted to registers (loaded once from gmem).
// K/V staged via cp.async. 16 s-blocks of 64.
// smem (floats):  Ks [64 c][72]      (stride 72  ≡ 8 mod 32)
//                 Vs [64 c'][68]     (stride 68  ≡ 4)
//                 Ps [8 w][16 t][68] (stride 68  ≡ 4)
// ===========================================================================
#define KSTR 72
#define VSTR 68
#define PSTR 68
#define SM_K 0
#define SM_V (64 * KSTR)              // 4608
#define SM_P (SM_V + 64 * VSTR)       // 8960
#define SM_TOT (SM_P + 8 * 16 * PSTR) // 17664 floats = 70656 B

__global__ void __launch_bounds__(256, 2) k_flash() {
    extern __shared__ float sm[];
    float* Ks = sm + SM_K;
    float* Vs = sm + SM_V;
    float* Ps = sm + SM_P;

    const int bh = blockIdx.y;
    const int b = bh >> 3, h = bh & 7;
    const int t0 = blockIdx.x * 128;
    const float* qb = g_qkv + ((size_t)b * 1536 + (size_t)h * 192) * NN;
    const float* kb = qb + (size_t)64 * NN;
    const float* vb = qb + (size_t)128 * NN;

    const int tid = threadIdx.x;
    const int w = tid >> 5, lane = tid & 31;
    const int grp = lane >> 2, tig = lane & 3;

    const uint32_t sK = sptr(Ks), sV = sptr(Vs);

    // Hoist Q fragments: invariant across the whole s-loop.
    // a0=[c=kk*8+tig][t=w*16+grp], a1=+8t, a2=c+4, a3=both  (values pre-rounded)
    uint32_t qf[8][4];
    {
        const float* p0 = qb + (size_t)tig * NN + t0 + w * 16 + grp;
        #pragma unroll
        for (int kk = 0; kk < 8; kk++) {
            const float* p = p0 + (size_t)(kk * 8) * NN;
            qf[kk][0] = __float_as_uint(p[0]);
            qf[kk][1] = __float_as_uint(p[8]);
            qf[kk][2] = __float_as_uint(p[(size_t)4 * NN]);
            qf[kk][3] = __float_as_uint(p[(size_t)4 * NN + 8]);
        }
    }

    float m0 = -1e30f, m1 = -1e30f, l0 = 0.f, l1 = 0.f;
    float O[8][4];
    #pragma unroll
    for (int j = 0; j < 8; j++)
        #pragma unroll
        for (int e = 0; e < 4; e++) O[j][e] = 0.f;

    for (int s0 = 0; s0 < NN; s0 += 64) {
        __syncthreads();   // previous iter's consumers done with Ks/Vs
        // Stage K,V via cp.async: 64x64 floats each = 1024 chunks each, 4/thread.
        #pragma unroll
        for (int p = 0; p < 4; p++) {
            int i = tid + p * 256;
            int c = i >> 4, s4 = (i & 15) * 4;
            cp16(sK + (uint32_t)(c * KSTR + s4) * 4, kb + (size_t)c * NN + s0 + s4);
            cp16(sV + (uint32_t)(c * VSTR + s4) * 4, vb + (size_t)c * NN + s0 + s4);
        }
        CP_COMMIT();
        CP_WAIT0();
        __syncthreads();

        // S = Q^T K : M=16 (warp t-rows), N=64 (s), K=64 (c)
        float acc[8][4];
        #pragma unroll
        for (int j = 0; j < 8; j++)
            #pragma unroll
            for (int e = 0; e < 4; e++) acc[j][e] = 0.f;

        #pragma unroll
        for (int kk = 0; kk < 8; kk++) {
            #pragma unroll
            for (int j = 0; j < 8; j++) {
                uint32_t bf[2];
                int bb = (kk * 8 + tig) * KSTR + j * 8 + grp;
                bf[0] = __float_as_uint(Ks[bb]);
                bf[1] = __float_as_uint(Ks[bb + 4 * KSTR]);
                mma_tf32(acc[j], qf[kk], bf);
            }
        }

        // scale logits
        #pragma unroll
        for (int j = 0; j < 8; j++)
            #pragma unroll
            for (int e = 0; e < 4; e++) acc[j][e] *= 0.125f;

        // online softmax (rows t = w*16+grp and +8; cols spread over quad)
        float rx0 = -1e30f, rx1 = -1e30f;
        #pragma unroll
        for (int j = 0; j < 8; j++) {
            rx0 = fmaxf(rx0, fmaxf(acc[j][0], acc[j][1]));
            rx1 = fmaxf(rx1, fmaxf(acc[j][2], acc[j][3]));
        }
        rx0 = fmaxf(rx0, __shfl_xor_sync(0xffffffffu, rx0, 1));
        rx0 = fmaxf(rx0, __shfl_xor_sync(0xffffffffu, rx0, 2));
        rx1 = fmaxf(rx1, __shfl_xor_sync(0xffffffffu, rx1, 1));
        rx1 = fmaxf(rx1, __shfl_xor_sync(0xffffffffu, rx1, 2));

        float mn0 = fmaxf(m0, rx0), mn1 = fmaxf(m1, rx1);
        float al0 = __expf(m0 - mn0), al1 = __expf(m1 - mn1);
        m0 = mn0; m1 = mn1;

        float rs0 = 0.f, rs1 = 0.f;
        float* pw = Ps + w * 16 * PSTR;
        #pragma unroll
        for (int j = 0; j < 8; j++) {
            float p0 = __expf(acc[j][0] - mn0);
            float p1 = __expf(acc[j][1] - mn0);
            float p2 = __expf(acc[j][2] - mn1);
            float p3 = __expf(acc[j][3] - mn1);
            rs0 += p0 + p1; rs1 += p2 + p3;
            int col = j * 8 + tig * 2;
            float2 q01 = { totf(p0), totf(p1) };
            float2 q23 = { totf(p2), totf(p3) };
            *(float2*)(pw + grp * PSTR + col) = q01;
            *(float2*)(pw + (grp + 8) * PSTR + col) = q23;
        }
        rs0 += __shfl_xor_sync(0xffffffffu, rs0, 1);
        rs0 += __shfl_xor_sync(0xffffffffu, rs0, 2);
        rs1 += __shfl_xor_sync(0xffffffffu, rs1, 1);
        rs1 += __shfl_xor_sync(0xffffffffu, rs1, 2);
        l0 = l0 * al0 + rs0;
        l1 = l1 * al1 + rs1;

        #pragma unroll
        for (int j = 0; j < 8; j++) {
            O[j][0] *= al0; O[j][1] *= al0;
            O[j][2] *= al1; O[j][3] *= al1;
        }
        __syncwarp();

        // O += P V^T : M=16 (t), N=64 (c'), K=64 (s)
        #pragma unroll
        for (int kk = 0; kk < 8; kk++) {
            uint32_t a[4];
            int ab = w * 16 * PSTR + grp * PSTR + kk * 8 + tig;
            a[0] = __float_as_uint(Ps[ab]);
            a[1] = __float_as_uint(Ps[ab + 8 * PSTR]);
            a[2] = __float_as_uint(Ps[ab + 4]);
            a[3] = __float_as_uint(Ps[ab + 8 * PSTR + 4]);
            #pragma unroll
            for (int j = 0; j < 8; j++) {
                uint32_t bf[2];
                int bb = (j * 8 + grp) * VSTR + kk * 8 + tig;
                bf[0] = __float_as_uint(Vs[bb]);
                bf[1] = __float_as_uint(Vs[bb + 4]);
                mma_tf32(O[j], a, bf);
            }
        }
    }

    // epilogue: normalize, round (producer-side tf32) and write
    float inv0 = 1.f / l0, inv1 = 1.f / l1;
    float* ob = g_attn + ((size_t)b * CC + (size_t)h * 64) * NN + t0;
    int tr0 = w * 16 + grp, tr1 = tr0 + 8;
    #pragma unroll
    for (int j = 0; j < 8; j++) {
        int c0 = j * 8 + tig * 2;
        ob[(size_t)c0 * NN + tr0]       = totf(O[j][0] * inv0);
        ob[(size_t)(c0 + 1) * NN + tr0] = totf(O[j][1] * inv0);
        ob[(size_t)c0 * NN + tr1]       = totf(O[j][2] * inv1);
        ob[(size_t)(c0 + 1) * NN + tr1] = totf(O[j][3] * inv1);
    }
}

// ===========================================================================
// GroupNorm kernels
// ===========================================================================
__global__ void gn1_kernel(const float* __restrict__ x,
                           const float* __restrict__ sc,
                           const float* __restrict__ bi) {
    const int blk = blockIdx.x;
    const int b = blk / GG, g = blk % GG;
    const size_t base = ((size_t)b * CC + (size_t)g * CPG) * NN;
    const float* xp = x + base;
    const int tid = threadIdx.x;

    float s = 0.f, s2 = 0.f;
    for (int i = tid; i < CPG * NN; i += 256) {
        float v = xp[i];
        s += v; s2 += v * v;
    }
    __shared__ float r1[256], r2[256];
    r1[tid] = s; r2[tid] = s2;
    __syncthreads();
    for (int o = 128; o > 0; o >>= 1) {
        if (tid < o) { r1[tid] += r1[tid + o]; r2[tid] += r2[tid + o]; }
        __syncthreads();
    }
    __shared__ float mu_s, rstd_s;
    if (tid == 0) {
        float inv = 1.0f / (CPG * NN);
        float mu = r1[0] * inv;
        float var = r2[0] * inv - mu * mu;
        mu_s = mu; rstd_s = rsqrtf(var + EPSV);
    }
    __syncthreads();
    const float mu = mu_s, rstd = rstd_s;
    for (int i = tid; i < CPG * NN; i += 256) {
        int c = g * CPG + (i >> 10);
        g_hn[base + i] = totf((xp[i] - mu) * rstd * sc[c] + bi[c]);
    }
}

__global__ void gn2_res_kernel(const float* __restrict__ x,
                               const float* __restrict__ sc,
                               const float* __restrict__ bi,
                               float* __restrict__ out) {
    const int blk = blockIdx.x;
    const int b = blk / GG, g = blk % GG;
    const size_t base = ((size_t)b * CC + (size_t)g * CPG) * NN;
    const float* yp = g_proj + base;
    const int tid = threadIdx.x;

    float s = 0.f, s2 = 0.f;
    for (int i = tid; i < CPG * NN; i += 256) {
        float v = yp[i];
        s += v; s2 += v * v;
    }
    __shared__ float r1[256], r2[256];
    r1[tid] = s; r2[tid] = s2;
    __syncthreads();
    for (int o = 128; o > 0; o >>= 1) {
        if (tid < o) { r1[tid] += r1[tid + o]; r2[tid] += r2[tid + o]; }
        __syncthreads();
    }
    __shared__ float mu_s, rstd_s;
    if (tid == 0) {
        float inv = 1.0f / (CPG * NN);
        float mu = r1[0] * inv;
        float var = r2[0] * inv - mu * mu;
        mu_s = mu; rstd_s = rsqrtf(var + EPSV);
    }
    __syncthreads();
    const float mu = mu_s, rstd = rstd_s;
    for (int i = tid; i < CPG * NN; i += 256) {
        int c = g * CPG + (i >> 10);
        out[base + i] = x[base + i] + (yp[i] - mu) * rstd * sc[c] + bi[c];
    }
}

// ---------------------------------------------------------------------------
extern "C" void kernel_launch(void* const* d_in, const int* in_sizes, int n_in,
                              void* d_out, int out_size) {
    const float* x        = (const float*)d_in[0];
    const float* gn1_s    = (const float*)d_in[1];
    const float* gn1_b    = (const float*)d_in[2];
    const float* w_qkv    = (const float*)d_in[3];
    const float* b_qkv    = (const float*)d_in[4];
    const float* w_proj   = (const float*)d_in[5];
    const float* b_proj   = (const float*)d_in[6];
    const float* gn2_s    = (const float*)d_in[7];
    const float* gn2_b    = (const float*)d_in[8];
    float* out = (float*)d_out;

    const int FSMEM = SM_TOT * (int)sizeof(float);   // 70656 B
    cudaFuncSetAttribute(k_flash, cudaFuncAttributeMaxDynamicSharedMemorySize, FSMEM);
    cudaFuncSetAttribute(k_qkv,  cudaFuncAttributeMaxDynamicSharedMemorySize, GEMM_SMEM);
    cudaFuncSetAttribute(k_proj, cudaFuncAttributeMaxDynamicSharedMemorySize, GEMM_SMEM);

    // 0) round weights to tf32 (producer-side rounding)
    k_roundw<<<(3 * CC * CC + CC * CC) / 256, 256>>>(w_qkv, w_proj);
    // 1) GroupNorm1 (writes tf32-rounded hn)
    gn1_kernel<<<BB * GG, 256>>>(x, gn1_s, gn1_b);
    // 2) QKV: [8] x (1536 x 1024 x 512), rounded output
    k_qkv<<<dim3(8, 12, BB), 256, GEMM_SMEM>>>(b_qkv);
    // 3) Fused flash attention: 8 t-tiles x 64 bh, rounded output
    k_flash<<<dim3(8, 64), 256, FSMEM>>>();
    // 4) proj: [8] x (512 x 1024 x 512), raw output
    k_proj<<<dim3(8, 4, BB), 256, GEMM_SMEM>>>(b_proj);
    // 5) GroupNorm2 + residual
    gn2_res_kernel<<<BB * GG, 256>>>(x, gn2_s, gn2_b, out);
}

// round 11
// speedup vs baseline: 1.0204x; 1.0204x over previous
#include <cuda_runtime.h>
#include <cstdint>

// Problem constants
#define BB      8
#define CC      512
#define NN      1024      // H*W
#define NH      8
#define GG      32        // groups
#define CPG     16        // channels per group
#define EPSV    1e-5f

// Scratch (device globals — no allocation allowed)
__device__ float g_hn  [(size_t)BB * CC * NN];          // GN1 output (tf32-rounded)
__device__ float g_qkv [(size_t)BB * 3 * CC * NN];      // qkv (tf32-rounded)
__device__ float g_attn[(size_t)BB * CC * NN];          // attention out (tf32-rounded)
__device__ float g_proj[(size_t)BB * CC * NN];          // proj out (raw fp32)
__device__ float g_wq  [(size_t)3 * CC * CC];           // rounded w_qkv
__device__ float g_wp  [(size_t)CC * CC];               // rounded w_proj

// ===========================================================================
// helpers
// ===========================================================================
__device__ __forceinline__ float totf(float x) {
    uint32_t r;
    asm("cvt.rna.tf32.f32 %0, %1;" : "=r"(r) : "f"(x));
    return __uint_as_float(r);
}

__device__ __forceinline__ void mma_tf32(float* c, const uint32_t* a, const uint32_t* b) {
    asm volatile(
        "mma.sync.aligned.m16n8k8.row.col.f32.tf32.tf32.f32 "
        "{%0,%1,%2,%3}, {%4,%5,%6,%7}, {%8,%9}, {%0,%1,%2,%3};"
        : "+f"(c[0]), "+f"(c[1]), "+f"(c[2]), "+f"(c[3])
        : "r"(a[0]), "r"(a[1]), "r"(a[2]), "r"(a[3]), "r"(b[0]), "r"(b[1]));
}

__device__ __forceinline__ uint32_t sptr(const void* p) {
    return (uint32_t)__cvta_generic_to_shared(p);
}
__device__ __forceinline__ void cp16(uint32_t dst, const void* src) {
    asm volatile("cp.async.cg.shared.global [%0], [%1], 16;" :: "r"(dst), "l"(src));
}
__device__ __forceinline__ void cp4(uint32_t dst, const void* src) {
    asm volatile("cp.async.ca.shared.global [%0], [%1], 4;" :: "r"(dst), "l"(src));
}
#define CP_COMMIT() asm volatile("cp.async.commit_group;" ::: "memory")
#define CP_WAIT2()  asm volatile("cp.async.wait_group 2;" ::: "memory")
#define CP_WAIT1()  asm volatile("cp.async.wait_group 1;" ::: "memory")
#define CP_WAIT0()  asm volatile("cp.async.wait_group 0;" ::: "memory")

// ===========================================================================
// Weight pre-rounding (w_qkv -> g_wq, w_proj -> g_wp)
// ===========================================================================
__global__ void k_roundw(const float* __restrict__ wq, const float* __restrict__ wp) {
    int i = blockIdx.x * 256 + threadIdx.x;
    const int NQ = 3 * CC * CC;   // 786432
    if (i < NQ) g_wq[i] = totf(wq[i]);
    else {
        int j = i - NQ;
        g_wp[j] = totf(wp[j]);
    }
}

// ===========================================================================
// Generic tf32 mma.sync GEMM with 4-stage cp.async pipeline.
//   D[c (128)][r (128)] = sum_k A[c][k] * B[k][r]
//   A: direct (src[c][k], pre-rounded), B: transpose (src[k][r], pre-rounded)
// 8 warps = 2 (M) x 4 (N); warp tile 64x32; mma m16n8k8; BK=16.
// dynamic smem: 4 stages x (As 128x20 + Bs 128x20) floats = 81920 B
// ===========================================================================
#define SPAD 20
#define STG_F (128 * SPAD)        // floats per operand-stage

template<bool RND>
__device__ __forceinline__ void gemm_core(
    const float* __restrict__ Asrc, int ldA,
    const float* __restrict__ Bsrc, int ldB,
    float* __restrict__ Out, const float* __restrict__ bias, int K)
{
    extern __shared__ float smem[];
    float* As = smem;                 // [4][STG_F]
    float* Bs = smem + 4 * STG_F;     // [4][STG_F]

    const int tid = threadIdx.x;
    const int wid = tid >> 5, lane = tid & 31;
    const int wm = wid & 1, wn = wid >> 1;
    const int grp = lane >> 2, tig = lane & 3;

    const uint32_t sA = sptr(As);
    const uint32_t sB = sptr(Bs);

    // A issue: 512 16B chunks, 2 per thread
    const int a_row0 = tid >> 2, a_kq = (tid & 3) * 4;
    const int a_row1 = (tid + 256) >> 2;
    // B issue (transpose): 2 tasks per thread, 4 x 4B each
    const int b_q0 = (wid * 2) & 3, b_r0 = ((wid * 2) >> 2) * 32 + lane;
    const int b_q1 = (wid * 2 + 1) & 3, b_r1 = ((wid * 2 + 1) >> 2) * 32 + lane;

    auto issue = [&](int it, int stage) {
        uint32_t da = sA + (uint32_t)(stage * STG_F) * 4;
        cp16(da + (a_row0 * SPAD + a_kq) * 4, Asrc + (size_t)a_row0 * ldA + it * 16 + a_kq);
        cp16(da + (a_row1 * SPAD + a_kq) * 4, Asrc + (size_t)a_row1 * ldA + it * 16 + a_kq);
        uint32_t db = sB + (uint32_t)(stage * STG_F) * 4;
        #pragma unroll
        for (int i = 0; i < 4; i++)
            cp4(db + (b_r0 * SPAD + b_q0 * 4 + i) * 4,
                Bsrc + (size_t)(it * 16 + b_q0 * 4 + i) * ldB + b_r0);
        #pragma unroll
        for (int i = 0; i < 4; i++)
            cp4(db + (b_r1 * SPAD + b_q1 * 4 + i) * 4,
                Bsrc + (size_t)(it * 16 + b_q1 * 4 + i) * ldB + b_r1);
    };

    float acc[4][4][4];
    #pragma unroll
    for (int i = 0; i < 4; i++)
        #pragma unroll
        for (int j = 0; j < 4; j++)
            #pragma unroll
            for (int e = 0; e < 4; e++) acc[i][j][e] = 0.f;

    const int nK = K >> 4;    // >= 32 here

    // prologue: 3 stages in flight
    issue(0, 0); CP_COMMIT();
    issue(1, 1); CP_COMMIT();
    issue(2, 2); CP_COMMIT();

    for (int it = 0; it < nK; it++) {
        CP_WAIT2();
        __syncthreads();

        if (it + 3 < nK) issue(it + 3, (it + 3) & 3);
        CP_COMMIT();    // real or empty — keeps group counting uniform

        const float* Ab = As + (it & 3) * STG_F;
        const float* Bb = Bs + (it & 3) * STG_F;
        #pragma unroll
        for (int kk = 0; kk < 2; kk++) {
            uint32_t a[4][4];
            #pragma unroll
            for (int i = 0; i < 4; i++) {
                int c = wm * 64 + i * 16 + grp;
                int k = kk * 8 + tig;
                a[i][0] = __float_as_uint(Ab[c * SPAD + k]);
                a[i][1] = __float_as_uint(Ab[(c + 8) * SPAD + k]);
                a[i][2] = __float_as_uint(Ab[c * SPAD + k + 4]);
                a[i][3] = __float_as_uint(Ab[(c + 8) * SPAD + k + 4]);
            }
            uint32_t b[4][2];
            #pragma unroll
            for (int j = 0; j < 4; j++) {
                int r = wn * 32 + j * 8 + grp;
                int k = kk * 8 + tig;
                b[j][0] = __float_as_uint(Bb[r * SPAD + k]);
                b[j][1] = __float_as_uint(Bb[r * SPAD + k + 4]);
            }
            #pragma unroll
            for (int i = 0; i < 4; i++)
                #pragma unroll
                for (int j = 0; j < 4; j++)
                    mma_tf32(acc[i][j], a[i], b[j]);
        }
    }

    #pragma unroll
    for (int i = 0; i < 4; i++) {
        int c = wm * 64 + i * 16 + grp;
        float bv0 = bias ? bias[c] : 0.f;
        float bv1 = bias ? bias[c + 8] : 0.f;
        #pragma unroll
        for (int j = 0; j < 4; j++) {
            int r = wn * 32 + j * 8 + tig * 2;
            float2 v0, v1;
            if (RND) {
                v0 = { totf(acc[i][j][0] + bv0), totf(acc[i][j][1] + bv0) };
                v1 = { totf(acc[i][j][2] + bv1), totf(acc[i][j][3] + bv1) };
            } else {
                v0 = { acc[i][j][0] + bv0, acc[i][j][1] + bv0 };
                v1 = { acc[i][j][2] + bv1, acc[i][j][3] + bv1 };
            }
            *(float2*)&Out[(size_t)c * NN + r] = v0;
            *(float2*)&Out[(size_t)(c + 8) * NN + r] = v1;
        }
    }
}

#define GEMM_SMEM (8 * STG_F * (int)sizeof(float))   // 81920 B

__global__ void __launch_bounds__(256, 2) k_qkv(const float* __restrict__ bias) {
    int n0 = blockIdx.x * 128, m0 = blockIdx.y * 128, b = blockIdx.z;
    gemm_core<true>(g_wq + (size_t)m0 * CC, CC,
                    g_hn + (size_t)b * CC * NN + n0, NN,
                    g_qkv + (size_t)b * 3 * CC * NN + (size_t)m0 * NN + n0,
                    bias + m0, CC);
}

__global__ void __launch_bounds__(256, 2) k_proj(const float* __restrict__ bias) {
    int n0 = blockIdx.x * 128, m0 = blockIdx.y * 128, b = blockIdx.z;
    gemm_core<false>(g_wp + (size_t)m0 * CC, CC,
                     g_attn + (size_t)b * CC * NN + n0, NN,
                     g_proj + (size_t)b * CC * NN + (size_t)m0 * NN + n0,
                     bias + m0, CC);
}

// ===========================================================================
// Flash attention (tf32 mma.sync, fused softmax), DOUBLE-BUFFERED K/V.
// One block = one (bh, 128-query tile). 8 warps; warp w owns t-rows
// [w*16, w*16+16). Q fragments hoisted to registers (0.125 scale folded in —
// exact power-of-two, tf32 mantissa unchanged). 16 s-blocks of 64; while
// block it is computed, block it+1 streams into the other K/V buffer.
// smem (floats):  Ks [2][64 c][72]   (stride 72  ≡ 8 mod 32)
//                 Vs [2][64 c'][68]  (stride 68  ≡ 4)
//                 Ps [8 w][16 t][68] (stride 68  ≡ 4)
// ===========================================================================
#define KSTR 72
#define VSTR 68
#define PSTR 68
#define KBUF (64 * KSTR)                    // 4608
#define VBUF (64 * VSTR)                    // 4352
#define SM_K 0
#define SM_V (2 * KBUF)                     // 9216
#define SM_P (SM_V + 2 * VBUF)              // 17920
#define SM_TOT (SM_P + 8 * 16 * PSTR)       // 26624 floats = 106496 B

__global__ void __launch_bounds__(256, 2) k_flash() {
    extern __shared__ float sm[];
    float* Ks = sm + SM_K;
    float* Vs = sm + SM_V;
    float* Ps = sm + SM_P;

    const int bh = blockIdx.y;
    const int b = bh >> 3, h = bh & 7;
    const int t0 = blockIdx.x * 128;
    const float* qb = g_qkv + ((size_t)b * 1536 + (size_t)h * 192) * NN;
    const float* kb = qb + (size_t)64 * NN;
    const float* vb = qb + (size_t)128 * NN;

    const int tid = threadIdx.x;
    const int w = tid >> 5, lane = tid & 31;
    const int grp = lane >> 2, tig = lane & 3;

    const uint32_t sK = sptr(Ks), sV = sptr(Vs);

    // cp.async staging for one s-block into buffer `buf`
    auto issue = [&](int sblk, int buf) {
        const int s0 = sblk * 64;
        #pragma unroll
        for (int p = 0; p < 4; p++) {
            int i = tid + p * 256;
            int c = i >> 4, s4 = (i & 15) * 4;
            cp16(sK + (uint32_t)(buf * KBUF + c * KSTR + s4) * 4,
                 kb + (size_t)c * NN + s0 + s4);
            cp16(sV + (uint32_t)(buf * VBUF + c * VSTR + s4) * 4,
                 vb + (size_t)c * NN + s0 + s4);
        }
    };

    // Hoist Q fragments (invariant across the s-loop), with 0.125 folded in.
    // ×0.125 is exact and keeps tf32 mantissa bits — numerically identical to
    // scaling the logits afterward.
    uint32_t qf[8][4];
    {
        const float* p0 = qb + (size_t)tig * NN + t0 + w * 16 + grp;
        #pragma unroll
        for (int kk = 0; kk < 8; kk++) {
            const float* p = p0 + (size_t)(kk * 8) * NN;
            qf[kk][0] = __float_as_uint(0.125f * p[0]);
            qf[kk][1] = __float_as_uint(0.125f * p[8]);
            qf[kk][2] = __float_as_uint(0.125f * p[(size_t)4 * NN]);
            qf[kk][3] = __float_as_uint(0.125f * p[(size_t)4 * NN + 8]);
        }
    }

    float m0 = -1e30f, m1 = -1e30f, l0 = 0.f, l1 = 0.f;
    float O[8][4];
    #pragma unroll
    for (int j = 0; j < 8; j++)
        #pragma unroll
        for (int e = 0; e < 4; e++) O[j][e] = 0.f;

    // prologue: stage s-block 0 into buffer 0
    issue(0, 0); CP_COMMIT();

    for (int it = 0; it < 16; it++) {
        // stream next block into the other buffer (guarded by the trailing
        // __syncthreads of the previous iteration)
        if (it + 1 < 16) { issue(it + 1, (it + 1) & 1); CP_COMMIT(); CP_WAIT1(); }
        else             { CP_WAIT0(); }
        __syncthreads();   // buffer `it&1` fully visible to all threads

        const float* Kb = Ks + (it & 1) * KBUF;
        const float* Vb = Vs + (it & 1) * VBUF;

        // S = (Q/8)^T K : M=16 (warp t-rows), N=64 (s), K=64 (c)
        float acc[8][4];
        #pragma unroll
        for (int j = 0; j < 8; j++)
            #pragma unroll
            for (int e = 0; e < 4; e++) acc[j][e] = 0.f;

        #pragma unroll
        for (int kk = 0; kk < 8; kk++) {
            #pragma unroll
            for (int j = 0; j < 8; j++) {
                uint32_t bf[2];
                int bb = (kk * 8 + tig) * KSTR + j * 8 + grp;
                bf[0] = __float_as_uint(Kb[bb]);
                bf[1] = __float_as_uint(Kb[bb + 4 * KSTR]);
                mma_tf32(acc[j], qf[kk], bf);
            }
        }

        // online softmax (rows t = w*16+grp and +8; cols spread over quad)
        float rx0 = -1e30f, rx1 = -1e30f;
        #pragma unroll
        for (int j = 0; j < 8; j++) {
            rx0 = fmaxf(rx0, fmaxf(acc[j][0], acc[j][1]));
            rx1 = fmaxf(rx1, fmaxf(acc[j][2], acc[j][3]));
        }
        rx0 = fmaxf(rx0, __shfl_xor_sync(0xffffffffu, rx0, 1));
        rx0 = fmaxf(rx0, __shfl_xor_sync(0xffffffffu, rx0, 2));
        rx1 = fmaxf(rx1, __shfl_xor_sync(0xffffffffu, rx1, 1));
        rx1 = fmaxf(rx1, __shfl_xor_sync(0xffffffffu, rx1, 2));

        float mn0 = fmaxf(m0, rx0), mn1 = fmaxf(m1, rx1);
        float al0 = __expf(m0 - mn0), al1 = __expf(m1 - mn1);
        m0 = mn0; m1 = mn1;

        float rs0 = 0.f, rs1 = 0.f;
        float* pw = Ps + w * 16 * PSTR;
        #pragma unroll
        for (int j = 0; j < 8; j++) {
            float p0 = __expf(acc[j][0] - mn0);
            float p1 = __expf(acc[j][1] - mn0);
            float p2 = __expf(acc[j][2] - mn1);
            float p3 = __expf(acc[j][3] - mn1);
            rs0 += p0 + p1; rs1 += p2 + p3;
            int col = j * 8 + tig * 2;
            float2 q01 = { totf(p0), totf(p1) };
            float2 q23 = { totf(p2), totf(p3) };
            *(float2*)(pw + grp * PSTR + col) = q01;
            *(float2*)(pw + (grp + 8) * PSTR + col) = q23;
        }
        rs0 += __shfl_xor_sync(0xffffffffu, rs0, 1);
        rs0 += __shfl_xor_sync(0xffffffffu, rs0, 2);
        rs1 += __shfl_xor_sync(0xffffffffu, rs1, 1);
        rs1 += __shfl_xor_sync(0xffffffffu, rs1, 2);
        l0 = l0 * al0 + rs0;
        l1 = l1 * al1 + rs1;

        #pragma unroll
        for (int j = 0; j < 8; j++) {
            O[j][0] *= al0; O[j][1] *= al0;
            O[j][2] *= al1; O[j][3] *= al1;
        }
        __syncwarp();

        // O += P V^T : M=16 (t), N=64 (c'), K=64 (s)
        #pragma unroll
        for (int kk = 0; kk < 8; kk++) {
            uint32_t a[4];
            int ab = w * 16 * PSTR + grp * PSTR + kk * 8 + tig;
            a[0] = __float_as_uint(Ps[ab]);
            a[1] = __float_as_uint(Ps[ab + 8 * PSTR]);
            a[2] = __float_as_uint(Ps[ab + 4]);
            a[3] = __float_as_uint(Ps[ab + 8 * PSTR + 4]);
            #pragma unroll
            for (int j = 0; j < 8; j++) {
                uint32_t bf[2];
                int bb = (j * 8 + grp) * VSTR + kk * 8 + tig;
                bf[0] = __float_as_uint(Vb[bb]);
                bf[1] = __float_as_uint(Vb[bb + 4]);
                mma_tf32(O[j], a, bf);
            }
        }
        __syncthreads();   // all warps done with buffer `it&1` before overwrite
    }

    // epilogue: normalize, round (producer-side tf32) and write
    float inv0 = 1.f / l0, inv1 = 1.f / l1;
    float* ob = g_attn + ((size_t)b * CC + (size_t)h * 64) * NN + t0;
    int tr0 = w * 16 + grp, tr1 = tr0 + 8;
    #pragma unroll
    for (int j = 0; j < 8; j++) {
        int c0 = j * 8 + tig * 2;
        ob[(size_t)c0 * NN + tr0]       = totf(O[j][0] * inv0);
        ob[(size_t)(c0 + 1) * NN + tr0] = totf(O[j][1] * inv0);
        ob[(size_t)c0 * NN + tr1]       = totf(O[j][2] * inv1);
        ob[(size_t)(c0 + 1) * NN + tr1] = totf(O[j][3] * inv1);
    }
}

// ===========================================================================
// GroupNorm kernels
// ===========================================================================
__global__ void gn1_kernel(const float* __restrict__ x,
                           const float* __restrict__ sc,
                           const float* __restrict__ bi) {
    const int blk = blockIdx.x;
    const int b = blk / GG, g = blk % GG;
    const size_t base = ((size_t)b * CC + (size_t)g * CPG) * NN;
    const float* xp = x + base;
    const int tid = threadIdx.x;

    float s = 0.f, s2 = 0.f;
    for (int i = tid; i < CPG * NN; i += 256) {
        float v = xp[i];
        s += v; s2 += v * v;
    }
    __shared__ float r1[256], r2[256];
    r1[tid] = s; r2[tid] = s2;
    __syncthreads();
    for (int o = 128; o > 0; o >>= 1) {
        if (tid < o) { r1[tid] += r1[tid + o]; r2[tid] += r2[tid + o]; }
        __syncthreads();
    }
    __shared__ float mu_s, rstd_s;
    if (tid == 0) {
        float inv = 1.0f / (CPG * NN);
        float mu = r1[0] * inv;
        float var = r2[0] * inv - mu * mu;
        mu_s = mu; rstd_s = rsqrtf(var + EPSV);
    }
    __syncthreads();
    const float mu = mu_s, rstd = rstd_s;
    for (int i = tid; i < CPG * NN; i += 256) {
        int c = g * CPG + (i >> 10);
        g_hn[base + i] = totf((xp[i] - mu) * rstd * sc[c] + bi[c]);
    }
}

__global__ void gn2_res_kernel(const float* __restrict__ x,
                               const float* __restrict__ sc,
                               const float* __restrict__ bi,
                               float* __restrict__ out) {
    const int blk = blockIdx.x;
    const int b = blk / GG, g = blk % GG;
    const size_t base = ((size_t)b * CC + (size_t)g * CPG) * NN;
    const float* yp = g_proj + base;
    const int tid = threadIdx.x;

    float s = 0.f, s2 = 0.f;
    for (int i = tid; i < CPG * NN; i += 256) {
        float v = yp[i];
        s += v; s2 += v * v;
    }
    __shared__ float r1[256], r2[256];
    r1[tid] = s; r2[tid] = s2;
    __syncthreads();
    for (int o = 128; o > 0; o >>= 1) {
        if (tid < o) { r1[tid] += r1[tid + o]; r2[tid] += r2[tid + o]; }
        __syncthreads();
    }
    __shared__ float mu_s, rstd_s;
    if (tid == 0) {
        float inv = 1.0f / (CPG * NN);
        float mu = r1[0] * inv;
        float var = r2[0] * inv - mu * mu;
        mu_s = mu; rstd_s = rsqrtf(var + EPSV);
    }
    __syncthreads();
    const float mu = mu_s, rstd = rstd_s;
    for (int i = tid; i < CPG * NN; i += 256) {
        int c = g * CPG + (i >> 10);
        out[base + i] = x[base + i] + (yp[i] - mu) * rstd * sc[c] + bi[c];
    }
}

// ---------------------------------------------------------------------------
extern "C" void kernel_launch(void* const* d_in, const int* in_sizes, int n_in,
                              void* d_out, int out_size) {
    const float* x        = (const float*)d_in[0];
    const float* gn1_s    = (const float*)d_in[1];
    const float* gn1_b    = (const float*)d_in[2];
    const float* w_qkv    = (const float*)d_in[3];
    const float* b_qkv    = (const float*)d_in[4];
    const float* w_proj   = (const float*)d_in[5];
    const float* b_proj   = (const float*)d_in[6];
    const float* gn2_s    = (const float*)d_in[7];
    const float* gn2_b    = (const float*)d_in[8];
    float* out = (float*)d_out;

    const int FSMEM = SM_TOT * (int)sizeof(float);   // 106496 B
    cudaFuncSetAttribute(k_flash, cudaFuncAttributeMaxDynamicSharedMemorySize, FSMEM);
    cudaFuncSetAttribute(k_qkv,  cudaFuncAttributeMaxDynamicSharedMemorySize, GEMM_SMEM);
    cudaFuncSetAttribute(k_proj, cudaFuncAttributeMaxDynamicSharedMemorySize, GEMM_SMEM);

    // 0) round weights to tf32 (producer-side rounding)
    k_roundw<<<(3 * CC * CC + CC * CC) / 256, 256>>>(w_qkv, w_proj);
    // 1) GroupNorm1 (writes tf32-rounded hn)
    gn1_kernel<<<BB * GG, 256>>>(x, gn1_s, gn1_b);
    // 2) QKV: [8] x (1536 x 1024 x 512), rounded output
    k_qkv<<<dim3(8, 12, BB), 256, GEMM_SMEM>>>(b_qkv);
    // 3) Fused flash attention (double-buffered K/V): 8 t-tiles x 64 bh
    k_flash<<<dim3(8, 64), 256, FSMEM>>>();
    // 4) proj: [8] x (512 x 1024 x 512), raw output
    k_proj<<<dim3(8, 4, BB), 256, GEMM_SMEM>>>(b_proj);
    // 5) GroupNorm2 + residual
    gn2_res_kernel<<<BB * GG, 256>>>(x, gn2_s, gn2_b, out);
}

// round 14
// speedup vs baseline: 1.0622x; 1.0410x over previous
#include <cuda_runtime.h>
#include <cstdint>

// Problem constants
#define BB      8
#define CC      512
#define NN      1024      // H*W
#define NH      8
#define GG      32        // groups
#define CPG     16        // channels per group
#define EPSV    1e-5f

// Scratch (device globals — no allocation allowed)
__device__ float g_hn  [(size_t)BB * CC * NN];          // GN1 output (tf32-rounded)
__device__ float g_qkv [(size_t)BB * 3 * CC * NN];      // qkv (tf32-rounded)
__device__ float g_attn[(size_t)BB * CC * NN];          // attention out (tf32-rounded)
__device__ float g_proj[(size_t)BB * CC * NN];          // proj out (raw fp32)
__device__ float g_wq  [(size_t)3 * CC * CC];           // rounded w_qkv
__device__ float g_wp  [(size_t)CC * CC];               // rounded w_proj

// ===========================================================================
// helpers
// ===========================================================================
__device__ __forceinline__ float totf(float x) {
    uint32_t r;
    asm("cvt.rna.tf32.f32 %0, %1;" : "=r"(r) : "f"(x));
    return __uint_as_float(r);
}

__device__ __forceinline__ void mma_tf32(float* c, const uint32_t* a, const uint32_t* b) {
    asm volatile(
        "mma.sync.aligned.m16n8k8.row.col.f32.tf32.tf32.f32 "
        "{%0,%1,%2,%3}, {%4,%5,%6,%7}, {%8,%9}, {%0,%1,%2,%3};"
        : "+f"(c[0]), "+f"(c[1]), "+f"(c[2]), "+f"(c[3])
        : "r"(a[0]), "r"(a[1]), "r"(a[2]), "r"(a[3]), "r"(b[0]), "r"(b[1]));
}

__device__ __forceinline__ uint32_t sptr(const void* p) {
    return (uint32_t)__cvta_generic_to_shared(p);
}
__device__ __forceinline__ void cp16(uint32_t dst, const void* src) {
    asm volatile("cp.async.cg.shared.global [%0], [%1], 16;" :: "r"(dst), "l"(src));
}
__device__ __forceinline__ void cp4(uint32_t dst, const void* src) {
    asm volatile("cp.async.ca.shared.global [%0], [%1], 4;" :: "r"(dst), "l"(src));
}
#define CP_COMMIT() asm volatile("cp.async.commit_group;" ::: "memory")
#define CP_WAIT2()  asm volatile("cp.async.wait_group 2;" ::: "memory")
#define CP_WAIT0()  asm volatile("cp.async.wait_group 0;" ::: "memory")

// ===========================================================================
// Weight pre-rounding (w_qkv -> g_wq, w_proj -> g_wp)
// ===========================================================================
__global__ void k_roundw(const float* __restrict__ wq, const float* __restrict__ wp) {
    int i = blockIdx.x * 256 + threadIdx.x;
    const int NQ = 3 * CC * CC;   // 786432
    if (i < NQ) g_wq[i] = totf(wq[i]);
    else {
        int j = i - NQ;
        g_wp[j] = totf(wp[j]);
    }
}

// ===========================================================================
// Generic tf32 mma.sync GEMM with 4-stage cp.async pipeline.
//   D[c (128)][r (128)] = sum_k A[c][k] * B[k][r]
// ===========================================================================
#define SPAD 20
#define STG_F (128 * SPAD)        // floats per operand-stage

template<bool RND>
__device__ __forceinline__ void gemm_core(
    const float* __restrict__ Asrc, int ldA,
    const float* __restrict__ Bsrc, int ldB,
    float* __restrict__ Out, const float* __restrict__ bias, int K)
{
    extern __shared__ float smem[];
    float* As = smem;                 // [4][STG_F]
    float* Bs = smem + 4 * STG_F;     // [4][STG_F]

    const int tid = threadIdx.x;
    const int wid = tid >> 5, lane = tid & 31;
    const int wm = wid & 1, wn = wid >> 1;
    const int grp = lane >> 2, tig = lane & 3;

    const uint32_t sA = sptr(As);
    const uint32_t sB = sptr(Bs);

    const int a_row0 = tid >> 2, a_kq = (tid & 3) * 4;
    const int a_row1 = (tid + 256) >> 2;
    const int b_q0 = (wid * 2) & 3, b_r0 = ((wid * 2) >> 2) * 32 + lane;
    const int b_q1 = (wid * 2 + 1) & 3, b_r1 = ((wid * 2 + 1) >> 2) * 32 + lane;

    auto issue = [&](int it, int stage) {
        uint32_t da = sA + (uint32_t)(stage * STG_F) * 4;
        cp16(da + (a_row0 * SPAD + a_kq) * 4, Asrc + (size_t)a_row0 * ldA + it * 16 + a_kq);
        cp16(da + (a_row1 * SPAD + a_kq) * 4, Asrc + (size_t)a_row1 * ldA + it * 16 + a_kq);
        uint32_t db = sB + (uint32_t)(stage * STG_F) * 4;
        #pragma unroll
        for (int i = 0; i < 4; i++)
            cp4(db + (b_r0 * SPAD + b_q0 * 4 + i) * 4,
                Bsrc + (size_t)(it * 16 + b_q0 * 4 + i) * ldB + b_r0);
        #pragma unroll
        for (int i = 0; i < 4; i++)
            cp4(db + (b_r1 * SPAD + b_q1 * 4 + i) * 4,
                Bsrc + (size_t)(it * 16 + b_q1 * 4 + i) * ldB + b_r1);
    };

    float acc[4][4][4];
    #pragma unroll
    for (int i = 0; i < 4; i++)
        #pragma unroll
        for (int j = 0; j < 4; j++)
            #pragma unroll
            for (int e = 0; e < 4; e++) acc[i][j][e] = 0.f;

    const int nK = K >> 4;

    issue(0, 0); CP_COMMIT();
    issue(1, 1); CP_COMMIT();
    issue(2, 2); CP_COMMIT();

    for (int it = 0; it < nK; it++) {
        CP_WAIT2();
        __syncthreads();

        if (it + 3 < nK) issue(it + 3, (it + 3) & 3);
        CP_COMMIT();

        const float* Ab = As + (it & 3) * STG_F;
        const float* Bb = Bs + (it & 3) * STG_F;
        #pragma unroll
        for (int kk = 0; kk < 2; kk++) {
            uint32_t a[4][4];
            #pragma unroll
            for (int i = 0; i < 4; i++) {
                int c = wm * 64 + i * 16 + grp;
                int k = kk * 8 + tig;
                a[i][0] = __float_as_uint(Ab[c * SPAD + k]);
                a[i][1] = __float_as_uint(Ab[(c + 8) * SPAD + k]);
                a[i][2] = __float_as_uint(Ab[c * SPAD + k + 4]);
                a[i][3] = __float_as_uint(Ab[(c + 8) * SPAD + k + 4]);
            }
            uint32_t b[4][2];
            #pragma unroll
            for (int j = 0; j < 4; j++) {
                int r = wn * 32 + j * 8 + grp;
                int k = kk * 8 + tig;
                b[j][0] = __float_as_uint(Bb[r * SPAD + k]);
                b[j][1] = __float_as_uint(Bb[r * SPAD + k + 4]);
            }
            #pragma unroll
            for (int i = 0; i < 4; i++)
                #pragma unroll
                for (int j = 0; j < 4; j++)
                    mma_tf32(acc[i][j], a[i], b[j]);
        }
    }

    #pragma unroll
    for (int i = 0; i < 4; i++) {
        int c = wm * 64 + i * 16 + grp;
        float bv0 = bias ? bias[c] : 0.f;
        float bv1 = bias ? bias[c + 8] : 0.f;
        #pragma unroll
        for (int j = 0; j < 4; j++) {
            int r = wn * 32 + j * 8 + tig * 2;
            float2 v0, v1;
            if (RND) {
                v0 = { totf(acc[i][j][0] + bv0), totf(acc[i][j][1] + bv0) };
                v1 = { totf(acc[i][j][2] + bv1), totf(acc[i][j][3] + bv1) };
            } else {
                v0 = { acc[i][j][0] + bv0, acc[i][j][1] + bv0 };
                v1 = { acc[i][j][2] + bv1, acc[i][j][3] + bv1 };
            }
            *(float2*)&Out[(size_t)c * NN + r] = v0;
            *(float2*)&Out[(size_t)(c + 8) * NN + r] = v1;
        }
    }
}

#define GEMM_SMEM (8 * STG_F * (int)sizeof(float))   // 81920 B

__global__ void __launch_bounds__(256, 2) k_qkv(const float* __restrict__ bias) {
    int n0 = blockIdx.x * 128, m0 = blockIdx.y * 128, b = blockIdx.z;
    gemm_core<true>(g_wq + (size_t)m0 * CC, CC,
                    g_hn + (size_t)b * CC * NN + n0, NN,
                    g_qkv + (size_t)b * 3 * CC * NN + (size_t)m0 * NN + n0,
                    bias + m0, CC);
}

__global__ void __launch_bounds__(256, 2) k_proj(const float* __restrict__ bias) {
    int n0 = blockIdx.x * 128, m0 = blockIdx.y * 128, b = blockIdx.z;
    gemm_core<false>(g_wp + (size_t)m0 * CC, CC,
                     g_attn + (size_t)b * CC * NN + n0, NN,
                     g_proj + (size_t)b * CC * NN + (size_t)m0 * NN + n0,
                     bias + m0, CC);
}

// ===========================================================================
// Flash attention (tf32 mma.sync, fused softmax) — SMALL-BLOCK VARIANT.
// 128 threads (4 warps), t-tile 64, one (bh, t-tile) per block; 4 blocks/SM
// (smem 53.2 KB). Single K/V buffer; K(it+1) re-issued early (after the
// post-S-MMA barrier) so its load overlaps softmax+PV; cross-block overlap
// hides the rest. Warp w owns t-rows [w*16, w*16+16). 16 s-blocks of 64.
// smem (floats):  Ks [64 c][72]      (stride 72 ≡ 8 mod 32)
//                 Vs [64 c'][68]     (stride 68 ≡ 4)
//                 Ps [4 w][16 t][68] (stride 68 ≡ 4)
// ===========================================================================
#define KSTR 72
#define VSTR 68
#define PSTR 68
#define SM_K 0
#define SM_V (64 * KSTR)                    // 4608
#define SM_P (SM_V + 64 * VSTR)             // 8960
#define SM_TOT (SM_P + 4 * 16 * PSTR)       // 13312 floats = 53248 B

__global__ void __launch_bounds__(128, 4) k_flash() {
    extern __shared__ float sm[];
    float* Ks = sm + SM_K;
    float* Vs = sm + SM_V;
    float* Ps = sm + SM_P;

    const int bh = blockIdx.y;
    const int b = bh >> 3, h = bh & 7;
    const int t0 = blockIdx.x * 64;
    const float* qb = g_qkv + ((size_t)b * 1536 + (size_t)h * 192) * NN;
    const float* kb = qb + (size_t)64 * NN;
    const float* vb = qb + (size_t)128 * NN;

    const int tid = threadIdx.x;
    const int w = tid >> 5, lane = tid & 31;
    const int grp = lane >> 2, tig = lane & 3;

    const uint32_t sK = sptr(Ks), sV = sptr(Vs);

    // stage one 64x64 operand tile (1024 cp16 chunks, 8 per thread)
    auto issueK = [&](int sblk) {
        const int s0 = sblk * 64;
        #pragma unroll
        for (int p = 0; p < 8; p++) {
            int i = tid + p * 128;
            int c = i >> 4, s4 = (i & 15) * 4;
            cp16(sK + (uint32_t)(c * KSTR + s4) * 4, kb + (size_t)c * NN + s0 + s4);
        }
    };
    auto issueV = [&](int sblk) {
        const int s0 = sblk * 64;
        #pragma unroll
        for (int p = 0; p < 8; p++) {
            int i = tid + p * 128;
            int c = i >> 4, s4 = (i & 15) * 4;
            cp16(sV + (uint32_t)(c * VSTR + s4) * 4, vb + (size_t)c * NN + s0 + s4);
        }
    };

    // Hoist Q fragments (invariant across the s-loop), 0.125 folded in
    // (exact power-of-two, tf32 mantissa unchanged).
    uint32_t qf[8][4];
    {
        const float* p0 = qb + (size_t)tig * NN + t0 + w * 16 + grp;
        #pragma unroll
        for (int kk = 0; kk < 8; kk++) {
            const float* p = p0 + (size_t)(kk * 8) * NN;
            qf[kk][0] = __float_as_uint(0.125f * p[0]);
            qf[kk][1] = __float_as_uint(0.125f * p[8]);
            qf[kk][2] = __float_as_uint(0.125f * p[(size_t)4 * NN]);
            qf[kk][3] = __float_as_uint(0.125f * p[(size_t)4 * NN + 8]);
        }
    }

    float m0 = -1e30f, m1 = -1e30f, l0 = 0.f, l1 = 0.f;
    float O[8][4];
    #pragma unroll
    for (int j = 0; j < 8; j++)
        #pragma unroll
        for (int e = 0; e < 4; e++) O[j][e] = 0.f;

    // prologue: stage s-block 0
    issueK(0); CP_COMMIT();
    issueV(0); CP_COMMIT();

    for (int it = 0; it < 16; it++) {
        CP_WAIT0();
        __syncthreads();   // K(it), V(it) visible; prior-iter consumers done

        // S = (Q/8)^T K : M=16 (warp t-rows), N=64 (s), K=64 (c)
        float acc[8][4];
        #pragma unroll
        for (int j = 0; j < 8; j++)
            #pragma unroll
            for (int e = 0; e < 4; e++) acc[j][e] = 0.f;

        #pragma unroll
        for (int kk = 0; kk < 8; kk++) {
            #pragma unroll
            for (int j = 0; j < 8; j++) {
                uint32_t bf[2];
                int bb = (kk * 8 + tig) * KSTR + j * 8 + grp;
                bf[0] = __float_as_uint(Ks[bb]);
                bf[1] = __float_as_uint(Ks[bb + 4 * KSTR]);
                mma_tf32(acc[j], qf[kk], bf);
            }
        }

        __syncthreads();   // all warps done reading K buffer
        if (it + 1 < 16) { issueK(it + 1); CP_COMMIT(); }  // overlaps softmax+PV

        // online softmax (rows t = w*16+grp and +8; cols spread over quad)
        float rx0 = -1e30f, rx1 = -1e30f;
        #pragma unroll
        for (int j = 0; j < 8; j++) {
            rx0 = fmaxf(rx0, fmaxf(acc[j][0], acc[j][1]));
            rx1 = fmaxf(rx1, fmaxf(acc[j][2], acc[j][3]));
        }
        rx0 = fmaxf(rx0, __shfl_xor_sync(0xffffffffu, rx0, 1));
        rx0 = fmaxf(rx0, __shfl_xor_sync(0xffffffffu, rx0, 2));
        rx1 = fmaxf(rx1, __shfl_xor_sync(0xffffffffu, rx1, 1));
        rx1 = fmaxf(rx1, __shfl_xor_sync(0xffffffffu, rx1, 2));

        float mn0 = fmaxf(m0, rx0), mn1 = fmaxf(m1, rx1);
        float al0 = __expf(m0 - mn0), al1 = __expf(m1 - mn1);
        m0 = mn0; m1 = mn1;

        float rs0 = 0.f, rs1 = 0.f;
        float* pw = Ps + w * 16 * PSTR;
        #pragma unroll
        for (int j = 0; j < 8; j++) {
            float p0 = __expf(acc[j][0] - mn0);
            float p1 = __expf(acc[j][1] - mn0);
            float p2 = __expf(acc[j][2] - mn1);
            float p3 = __expf(acc[j][3] - mn1);
            rs0 += p0 + p1; rs1 += p2 + p3;
            int col = j * 8 + tig * 2;
            float2 q01 = { totf(p0), totf(p1) };
            float2 q23 = { totf(p2), totf(p3) };
            *(float2*)(pw + grp * PSTR + col) = q01;
            *(float2*)(pw + (grp + 8) * PSTR + col) = q23;
        }
        rs0 += __shfl_xor_sync(0xffffffffu, rs0, 1);
        rs0 += __shfl_xor_sync(0xffffffffu, rs0, 2);
        rs1 += __shfl_xor_sync(0xffffffffu, rs1, 1);
        rs1 += __shfl_xor_sync(0xffffffffu, rs1, 2);
        l0 = l0 * al0 + rs0;
        l1 = l1 * al1 + rs1;

        #pragma unroll
        for (int j = 0; j < 8; j++) {
            O[j][0] *= al0; O[j][1] *= al0;
            O[j][2] *= al1; O[j][3] *= al1;
        }
        __syncwarp();

        // O += P V^T : M=16 (t), N=64 (c'), K=64 (s)
        #pragma unroll
        for (int kk = 0; kk < 8; kk++) {
            uint32_t a[4];
            int ab = w * 16 * PSTR + grp * PSTR + kk * 8 + tig;
            a[0] = __float_as_uint(Ps[ab]);
            a[1] = __float_as_uint(Ps[ab + 8 * PSTR]);
            a[2] = __float_as_uint(Ps[ab + 4]);
            a[3] = __float_as_uint(Ps[ab + 8 * PSTR + 4]);
            #pragma unroll
            for (int j = 0; j < 8; j++) {
                uint32_t bf[2];
                int bb = (j * 8 + grp) * VSTR + kk * 8 + tig;
                bf[0] = __float_as_uint(Vs[bb]);
                bf[1] = __float_as_uint(Vs[bb + 4]);
                mma_tf32(O[j], a, bf);
            }
        }

        __syncthreads();   // all warps done reading V buffer
        if (it + 1 < 16) { issueV(it + 1); CP_COMMIT(); }
    }

    // epilogue: normalize, round (producer-side tf32) and write
    float inv0 = 1.f / l0, inv1 = 1.f / l1;
    float* ob = g_attn + ((size_t)b * CC + (size_t)h * 64) * NN + t0;
    int tr0 = w * 16 + grp, tr1 = tr0 + 8;
    #pragma unroll
    for (int j = 0; j < 8; j++) {
        int c0 = j * 8 + tig * 2;
        ob[(size_t)c0 * NN + tr0]       = totf(O[j][0] * inv0);
        ob[(size_t)(c0 + 1) * NN + tr0] = totf(O[j][1] * inv0);
        ob[(size_t)c0 * NN + tr1]       = totf(O[j][2] * inv1);
        ob[(size_t)(c0 + 1) * NN + tr1] = totf(O[j][3] * inv1);
    }
}

// ===========================================================================
// GroupNorm kernels
// ===========================================================================
__global__ void gn1_kernel(const float* __restrict__ x,
                           const float* __restrict__ sc,
                           const float* __restrict__ bi) {
    const int blk = blockIdx.x;
    const int b = blk / GG, g = blk % GG;
    const size_t base = ((size_t)b * CC + (size_t)g * CPG) * NN;
    const float* xp = x + base;
    const int tid = threadIdx.x;

    float s = 0.f, s2 = 0.f;
    for (int i = tid; i < CPG * NN; i += 256) {
        float v = xp[i];
        s += v; s2 += v * v;
    }
    __shared__ float r1[256], r2[256];
    r1[tid] = s; r2[tid] = s2;
    __syncthreads();
    for (int o = 128; o > 0; o >>= 1) {
        if (tid < o) { r1[tid] += r1[tid + o]; r2[tid] += r2[tid + o]; }
        __syncthreads();
    }
    __shared__ float mu_s, rstd_s;
    if (tid == 0) {
        float inv = 1.0f / (CPG * NN);
        float mu = r1[0] * inv;
        float var = r2[0] * inv - mu * mu;
        mu_s = mu; rstd_s = rsqrtf(var + EPSV);
    }
    __syncthreads();
    const float mu = mu_s, rstd = rstd_s;
    for (int i = tid; i < CPG * NN; i += 256) {
        int c = g * CPG + (i >> 10);
        g_hn[base + i] = totf((xp[i] - mu) * rstd * sc[c] + bi[c]);
    }
}

__global__ void gn2_res_kernel(const float* __restrict__ x,
                               const float* __restrict__ sc,
                               const float* __restrict__ bi,
                               float* __restrict__ out) {
    const int blk = blockIdx.x;
    const int b = blk / GG, g = blk % GG;
    const size_t base = ((size_t)b * CC + (size_t)g * CPG) * NN;
    const float* yp = g_proj + base;
    const int tid = threadIdx.x;

    float s = 0.f, s2 = 0.f;
    for (int i = tid; i < CPG * NN; i += 256) {
        float v = yp[i];
        s += v; s2 += v * v;
    }
    __shared__ float r1[256], r2[256];
    r1[tid] = s; r2[tid] = s2;
    __syncthreads();
    for (int o = 128; o > 0; o >>= 1) {
        if (tid < o) { r1[tid] += r1[tid + o]; r2[tid] += r2[tid + o]; }
        __syncthreads();
    }
    __shared__ float mu_s, rstd_s;
    if (tid == 0) {
        float inv = 1.0f / (CPG * NN);
        float mu = r1[0] * inv;
        float var = r2[0] * inv - mu * mu;
        mu_s = mu; rstd_s = rsqrtf(var + EPSV);
    }
    __syncthreads();
    const float mu = mu_s, rstd = rstd_s;
    for (int i = tid; i < CPG * NN; i += 256) {
        int c = g * CPG + (i >> 10);
        out[base + i] = x[base + i] + (yp[i] - mu) * rstd * sc[c] + bi[c];
    }
}

// ---------------------------------------------------------------------------
extern "C" void kernel_launch(void* const* d_in, const int* in_sizes, int n_in,
                              void* d_out, int out_size) {
    const float* x        = (const float*)d_in[0];
    const float* gn1_s    = (const float*)d_in[1];
    const float* gn1_b    = (const float*)d_in[2];
    const float* w_qkv    = (const float*)d_in[3];
    const float* b_qkv    = (const float*)d_in[4];
    const float* w_proj   = (const float*)d_in[5];
    const float* b_proj   = (const float*)d_in[6];
    const float* gn2_s    = (const float*)d_in[7];
    const float* gn2_b    = (const float*)d_in[8];
    float* out = (float*)d_out;

    const int FSMEM = SM_TOT * (int)sizeof(float);   // 53248 B
    cudaFuncSetAttribute(k_flash, cudaFuncAttributeMaxDynamicSharedMemorySize, FSMEM);
    cudaFuncSetAttribute(k_qkv,  cudaFuncAttributeMaxDynamicSharedMemorySize, GEMM_SMEM);
    cudaFuncSetAttribute(k_proj, cudaFuncAttributeMaxDynamicSharedMemorySize, GEMM_SMEM);

    // 0) round weights to tf32 (producer-side rounding)
    k_roundw<<<(3 * CC * CC + CC * CC) / 256, 256>>>(w_qkv, w_proj);
    // 1) GroupNorm1 (writes tf32-rounded hn)
    gn1_kernel<<<BB * GG, 256>>>(x, gn1_s, gn1_b);
    // 2) QKV: [8] x (1536 x 1024 x 512), rounded output
    k_qkv<<<dim3(8, 12, BB), 256, GEMM_SMEM>>>(b_qkv);
    // 3) Fused flash attention: 16 t-tiles (64 each) x 64 bh, 128-thr blocks
    k_flash<<<dim3(16, 64), 128, FSMEM>>>();
    // 4) proj: [8] x (512 x 1024 x 512), raw output
    k_proj<<<dim3(8, 4, BB), 256, GEMM_SMEM>>>(b_proj);
    // 5) GroupNorm2 + residual
    gn2_res_kernel<<<BB * GG, 256>>>(x, gn2_s, gn2_b, out);
}

// round 15
// speedup vs baseline: 1.0836x; 1.0201x over previous
#include <cuda_runtime.h>
#include <cstdint>

// Problem constants
#define BB      8
#define CC      512
#define NN      1024      // H*W
#define NH      8
#define GG      32        // groups
#define CPG     16        // channels per group
#define EPSV    1e-5f

// Scratch (device globals — no allocation allowed)
__device__ float g_hn  [(size_t)BB * CC * NN];          // GN1 output (tf32-rounded)
__device__ float g_qkv [(size_t)BB * 3 * CC * NN];      // qkv (Q sections used)
__device__ float g_kp  [(size_t)BB * NH * 64 * NN];     // K pair-interleaved
__device__ float g_vp  [(size_t)BB * NH * 64 * NN];     // V column-pair-permuted
__device__ float g_attn[(size_t)BB * CC * NN];          // attention out (tf32-rounded)
__device__ float g_proj[(size_t)BB * CC * NN];          // proj out (raw fp32)
__device__ float g_wq  [(size_t)3 * CC * CC];           // rounded w_qkv
__device__ float g_wp  [(size_t)CC * CC];               // rounded w_proj

// ===========================================================================
// helpers
// ===========================================================================
__device__ __forceinline__ float totf(float x) {
    uint32_t r;
    asm("cvt.rna.tf32.f32 %0, %1;" : "=r"(r) : "f"(x));
    return __uint_as_float(r);
}

__device__ __forceinline__ void mma_tf32(float* c, const uint32_t* a, const uint32_t* b) {
    asm volatile(
        "mma.sync.aligned.m16n8k8.row.col.f32.tf32.tf32.f32 "
        "{%0,%1,%2,%3}, {%4,%5,%6,%7}, {%8,%9}, {%0,%1,%2,%3};"
        : "+f"(c[0]), "+f"(c[1]), "+f"(c[2]), "+f"(c[3])
        : "r"(a[0]), "r"(a[1]), "r"(a[2]), "r"(a[3]), "r"(b[0]), "r"(b[1]));
}

__device__ __forceinline__ uint32_t sptr(const void* p) {
    return (uint32_t)__cvta_generic_to_shared(p);
}
__device__ __forceinline__ void cp16(uint32_t dst, const void* src) {
    asm volatile("cp.async.cg.shared.global [%0], [%1], 16;" :: "r"(dst), "l"(src));
}
__device__ __forceinline__ void cp4(uint32_t dst, const void* src) {
    asm volatile("cp.async.ca.shared.global [%0], [%1], 4;" :: "r"(dst), "l"(src));
}
#define CP_COMMIT() asm volatile("cp.async.commit_group;" ::: "memory")
#define CP_WAIT2()  asm volatile("cp.async.wait_group 2;" ::: "memory")
#define CP_WAIT0()  asm volatile("cp.async.wait_group 0;" ::: "memory")

// ===========================================================================
// Weight pre-rounding (w_qkv -> g_wq, w_proj -> g_wp)
// ===========================================================================
__global__ void k_roundw(const float* __restrict__ wq, const float* __restrict__ wp) {
    int i = blockIdx.x * 256 + threadIdx.x;
    const int NQ = 3 * CC * CC;   // 786432
    if (i < NQ) g_wq[i] = totf(wq[i]);
    else {
        int j = i - NQ;
        g_wp[j] = totf(wp[j]);
    }
}

// ===========================================================================
// qkv output writer: routes Q -> g_qkv (normal), K -> g_kp (pair-interleaved),
// V -> g_vp (column-pair-permuted). All tf32-rounded. Section boundaries are
// 64-channel aligned; c and c+8 of one 16-channel window share a section.
//   g_kp per (b,h): 32 pairIdx rows of 2*NN floats; pairIdx = kk*4 + (u%4),
//     slot = u/4 where c_local = kk*8 + u. element (c_local, s) at
//     pairIdx*2NN + s*2 + slot  -> flash LDS.64 gets (K[c][s], K[c+4][s]).
//   g_vp per (b,h): 64 rows of NN; s permuted within 8-groups:
//     u<4 -> g8*8+u*2, else g8*8+(u-4)*2+1  -> (s, s+4) adjacent.
// ===========================================================================
__device__ __forceinline__ void qkv_write(int b, int c, int r, float x0, float x1) {
    int head = c / 192;
    int rem  = c % 192;
    int sec  = rem >> 6;        // 0=q, 1=k, 2=v
    int cl   = rem & 63;
    if (sec == 0) {
        float* o = g_qkv + ((size_t)b * 1536 + c) * NN + r;
        o[0] = totf(x0); o[1] = totf(x1);
    } else if (sec == 1) {
        int u = cl & 7, kk = cl >> 3;
        int t = u & 3, slot = u >> 2;
        size_t base = (((size_t)(b * 8 + head)) * 32 + kk * 4 + t) * (2 * NN)
                    + (size_t)r * 2 + slot;
        g_kp[base] = totf(x0); g_kp[base + 2] = totf(x1);
    } else {
        int g8 = r >> 3, u = r & 7;          // r even
        int p0 = (u < 4) ? (g8 * 8 + u * 2) : (g8 * 8 + (u - 4) * 2 + 1);
        int u1 = u + 1;
        int p1 = (u1 < 4) ? (g8 * 8 + u1 * 2) : (g8 * 8 + (u1 - 4) * 2 + 1);
        size_t base = (((size_t)(b * 8 + head)) * 64 + cl) * NN;
        g_vp[base + p0] = totf(x0); g_vp[base + p1] = totf(x1);
    }
}

// ===========================================================================
// Generic tf32 mma.sync GEMM with 4-stage cp.async pipeline.
//   D[c (128)][r (128)] = sum_k A[c][k] * B[k][r]
// EPI 0: plain write (+bias) to Out.  EPI 1: qkv_write routing (+bias).
// ===========================================================================
#define SPAD 20
#define STG_F (128 * SPAD)        // floats per operand-stage

template<int EPI>
__device__ __forceinline__ void gemm_core(
    const float* __restrict__ Asrc, int ldA,
    const float* __restrict__ Bsrc, int ldB,
    float* __restrict__ Out, const float* __restrict__ bias, int K,
    int bq, int m0, int n0)
{
    extern __shared__ float smem[];
    float* As = smem;                 // [4][STG_F]
    float* Bs = smem + 4 * STG_F;     // [4][STG_F]

    const int tid = threadIdx.x;
    const int wid = tid >> 5, lane = tid & 31;
    const int wm = wid & 1, wn = wid >> 1;
    const int grp = lane >> 2, tig = lane & 3;

    const uint32_t sA = sptr(As);
    const uint32_t sB = sptr(Bs);

    const int a_row0 = tid >> 2, a_kq = (tid & 3) * 4;
    const int a_row1 = (tid + 256) >> 2;
    const int b_q0 = (wid * 2) & 3, b_r0 = ((wid * 2) >> 2) * 32 + lane;
    const int b_q1 = (wid * 2 + 1) & 3, b_r1 = ((wid * 2 + 1) >> 2) * 32 + lane;

    auto issue = [&](int it, int stage) {
        uint32_t da = sA + (uint32_t)(stage * STG_F) * 4;
        cp16(da + (a_row0 * SPAD + a_kq) * 4, Asrc + (size_t)a_row0 * ldA + it * 16 + a_kq);
        cp16(da + (a_row1 * SPAD + a_kq) * 4, Asrc + (size_t)a_row1 * ldA + it * 16 + a_kq);
        uint32_t db = sB + (uint32_t)(stage * STG_F) * 4;
        #pragma unroll
        for (int i = 0; i < 4; i++)
            cp4(db + (b_r0 * SPAD + b_q0 * 4 + i) * 4,
                Bsrc + (size_t)(it * 16 + b_q0 * 4 + i) * ldB + b_r0);
        #pragma unroll
        for (int i = 0; i < 4; i++)
            cp4(db + (b_r1 * SPAD + b_q1 * 4 + i) * 4,
                Bsrc + (size_t)(it * 16 + b_q1 * 4 + i) * ldB + b_r1);
    };

    float acc[4][4][4];
    #pragma unroll
    for (int i = 0; i < 4; i++)
        #pragma unroll
        for (int j = 0; j < 4; j++)
            #pragma unroll
            for (int e = 0; e < 4; e++) acc[i][j][e] = 0.f;

    const int nK = K >> 4;

    issue(0, 0); CP_COMMIT();
    issue(1, 1); CP_COMMIT();
    issue(2, 2); CP_COMMIT();

    for (int it = 0; it < nK; it++) {
        CP_WAIT2();
        __syncthreads();

        if (it + 3 < nK) issue(it + 3, (it + 3) & 3);
        CP_COMMIT();

        const float* Ab = As + (it & 3) * STG_F;
        const float* Bb = Bs + (it & 3) * STG_F;
        #pragma unroll
        for (int kk = 0; kk < 2; kk++) {
            uint32_t a[4][4];
            #pragma unroll
            for (int i = 0; i < 4; i++) {
                int c = wm * 64 + i * 16 + grp;
                int k = kk * 8 + tig;
                a[i][0] = __float_as_uint(Ab[c * SPAD + k]);
                a[i][1] = __float_as_uint(Ab[(c + 8) * SPAD + k]);
                a[i][2] = __float_as_uint(Ab[c * SPAD + k + 4]);
                a[i][3] = __float_as_uint(Ab[(c + 8) * SPAD + k + 4]);
            }
            uint32_t b[4][2];
            #pragma unroll
            for (int j = 0; j < 4; j++) {
                int r = wn * 32 + j * 8 + grp;
                int k = kk * 8 + tig;
                b[j][0] = __float_as_uint(Bb[r * SPAD + k]);
                b[j][1] = __float_as_uint(Bb[r * SPAD + k + 4]);
            }
            #pragma unroll
            for (int i = 0; i < 4; i++)
                #pragma unroll
                for (int j = 0; j < 4; j++)
                    mma_tf32(acc[i][j], a[i], b[j]);
        }
    }

    #pragma unroll
    for (int i = 0; i < 4; i++) {
        int c = wm * 64 + i * 16 + grp;
        if (EPI == 0) {
            float bv0 = bias[c], bv1 = bias[c + 8];
            #pragma unroll
            for (int j = 0; j < 4; j++) {
                int r = wn * 32 + j * 8 + tig * 2;
                float2 v0 = { acc[i][j][0] + bv0, acc[i][j][1] + bv0 };
                float2 v1 = { acc[i][j][2] + bv1, acc[i][j][3] + bv1 };
                *(float2*)&Out[(size_t)c * NN + r] = v0;
                *(float2*)&Out[(size_t)(c + 8) * NN + r] = v1;
            }
        } else {
            int cg = m0 + c;
            float bv0 = bias[cg], bv1 = bias[cg + 8];
            #pragma unroll
            for (int j = 0; j < 4; j++) {
                int r = n0 + wn * 32 + j * 8 + tig * 2;
                qkv_write(bq, cg,     r, acc[i][j][0] + bv0, acc[i][j][1] + bv0);
                qkv_write(bq, cg + 8, r, acc[i][j][2] + bv1, acc[i][j][3] + bv1);
            }
        }
    }
}

#define GEMM_SMEM (8 * STG_F * (int)sizeof(float))   // 81920 B

__global__ void __launch_bounds__(256, 2) k_qkv(const float* __restrict__ bias) {
    int n0 = blockIdx.x * 128, m0 = blockIdx.y * 128, b = blockIdx.z;
    gemm_core<1>(g_wq + (size_t)m0 * CC, CC,
                 g_hn + (size_t)b * CC * NN + n0, NN,
                 nullptr, bias, CC, b, m0, n0);
}

__global__ void __launch_bounds__(256, 2) k_proj(const float* __restrict__ bias) {
    int n0 = blockIdx.x * 128, m0 = blockIdx.y * 128, b = blockIdx.z;
    gemm_core<0>(g_wp + (size_t)m0 * CC, CC,
                 g_attn + (size_t)b * CC * NN + n0, NN,
                 g_proj + (size_t)b * CC * NN + (size_t)m0 * NN + n0,
                 bias + m0, CC, 0, 0, 0);
}

// ===========================================================================
// Flash attention — paired-layout K/V (LDS.64 B-fragments), no max-subtract.
// 128 threads (4 warps), t-tile 64, 4 blocks/SM (smem 53.2 KB). Single K/V
// buffer, early K re-issue. Warp w owns t-rows [w*16, w*16+16).
// smem: KP [32 pair][128] stride 136 (≡8 mod 32, LDS.64 conflict-free)
//       VP [64 c'][64]    stride 72  (≡8)
//       Ps [4 w][16 t][68]
// ===========================================================================
#define KPSTR 136
#define VPSTR 72
#define PSTR  68
#define SM_KP 0
#define SM_VP (32 * KPSTR)                   // 4352
#define SM_P  (SM_VP + 64 * VPSTR)           // 8960
#define SM_TOT (SM_P + 4 * 16 * PSTR)        // 13312 floats = 53248 B

__global__ void __launch_bounds__(128, 4) k_flash() {
    extern __shared__ float sm[];
    float* KP = sm + SM_KP;
    float* VP = sm + SM_VP;
    float* Ps = sm + SM_P;

    const int bh = blockIdx.y;
    const int b = bh >> 3, h = bh & 7;
    const int t0 = blockIdx.x * 64;
    const float* qb  = g_qkv + ((size_t)b * 1536 + (size_t)h * 192) * NN;
    const float* kpb = g_kp + (size_t)bh * 64 * NN;   // 32 pairs x 2NN
    const float* vpb = g_vp + (size_t)bh * 64 * NN;   // 64 rows x NN

    const int tid = threadIdx.x;
    const int w = tid >> 5, lane = tid & 31;
    const int grp = lane >> 2, tig = lane & 3;

    const uint32_t sKP = sptr(KP), sVP = sptr(VP);

    // stage K pairs: 32 rows x 128 floats (s-block sblk covers cols sblk*128..+128)
    auto issueK = [&](int sblk) {
        const float* src = kpb + (size_t)sblk * 128;
        #pragma unroll
        for (int p = 0; p < 8; p++) {
            int i = tid + p * 128;
            int row = i >> 5, c16 = (i & 31) * 4;
            cp16(sKP + (uint32_t)(row * KPSTR + c16) * 4,
                 src + (size_t)row * 2 * NN + c16);
        }
    };
    // stage V permuted: 64 rows x 64 floats
    auto issueV = [&](int sblk) {
        const float* src = vpb + (size_t)sblk * 64;
        #pragma unroll
        for (int p = 0; p < 8; p++) {
            int i = tid + p * 128;
            int row = i >> 4, c16 = (i & 15) * 4;
            cp16(sVP + (uint32_t)(row * VPSTR + c16) * 4,
                 src + (size_t)row * NN + c16);
        }
    };

    // Hoist Q fragments (invariant across the s-loop), 0.125 folded in.
    uint32_t qf[8][4];
    {
        const float* p0 = qb + (size_t)tig * NN + t0 + w * 16 + grp;
        #pragma unroll
        for (int kk = 0; kk < 8; kk++) {
            const float* p = p0 + (size_t)(kk * 8) * NN;
            qf[kk][0] = __float_as_uint(0.125f * p[0]);
            qf[kk][1] = __float_as_uint(0.125f * p[8]);
            qf[kk][2] = __float_as_uint(0.125f * p[(size_t)4 * NN]);
            qf[kk][3] = __float_as_uint(0.125f * p[(size_t)4 * NN + 8]);
        }
    }

    float l0 = 0.f, l1 = 0.f;
    float O[8][4];
    #pragma unroll
    for (int j = 0; j < 8; j++)
        #pragma unroll
        for (int e = 0; e < 4; e++) O[j][e] = 0.f;

    issueK(0); CP_COMMIT();
    issueV(0); CP_COMMIT();

    for (int it = 0; it < 16; it++) {
        CP_WAIT0();
        __syncthreads();   // K(it), V(it) visible; prior-iter consumers done

        // S = (Q/8)^T K : B-fragment = one LDS.64 from paired K
        float acc[8][4];
        #pragma unroll
        for (int j = 0; j < 8; j++)
            #pragma unroll
            for (int e = 0; e < 4; e++) acc[j][e] = 0.f;

        #pragma unroll
        for (int kk = 0; kk < 8; kk++) {
            const float* kr = KP + (kk * 4 + tig) * KPSTR;
            #pragma unroll
            for (int j = 0; j < 8; j++) {
                float2 kv = *(const float2*)(kr + (j * 8 + grp) * 2);
                uint32_t bf[2] = { __float_as_uint(kv.x), __float_as_uint(kv.y) };
                mma_tf32(acc[j], qf[kk], bf);
            }
        }

        __syncthreads();   // all warps done reading K buffer
        if (it + 1 < 16) { issueK(it + 1); CP_COMMIT(); }  // overlaps softmax+PV

        // softmax without max-subtraction (|logit| < ~2 by construction):
        // p = exp(v); l += sum(p); normalize at the end. Exact softmax identity.
        float rs0 = 0.f, rs1 = 0.f;
        float* pw = Ps + w * 16 * PSTR;
        #pragma unroll
        for (int j = 0; j < 8; j++) {
            float p0 = __expf(acc[j][0]);
            float p1 = __expf(acc[j][1]);
            float p2 = __expf(acc[j][2]);
            float p3 = __expf(acc[j][3]);
            rs0 += p0 + p1; rs1 += p2 + p3;
            int col = j * 8 + tig * 2;
            float2 q01 = { totf(p0), totf(p1) };
            float2 q23 = { totf(p2), totf(p3) };
            *(float2*)(pw + grp * PSTR + col) = q01;
            *(float2*)(pw + (grp + 8) * PSTR + col) = q23;
        }
        rs0 += __shfl_xor_sync(0xffffffffu, rs0, 1);
        rs0 += __shfl_xor_sync(0xffffffffu, rs0, 2);
        rs1 += __shfl_xor_sync(0xffffffffu, rs1, 1);
        rs1 += __shfl_xor_sync(0xffffffffu, rs1, 2);
        l0 += rs0;
        l1 += rs1;
        __syncwarp();

        // O += P V^T : B-fragment = one LDS.64 from permuted V
        #pragma unroll
        for (int kk = 0; kk < 8; kk++) {
            uint32_t a[4];
            int ab = w * 16 * PSTR + grp * PSTR + kk * 8 + tig;
            a[0] = __float_as_uint(Ps[ab]);
            a[1] = __float_as_uint(Ps[ab + 8 * PSTR]);
            a[2] = __float_as_uint(Ps[ab + 4]);
            a[3] = __float_as_uint(Ps[ab + 8 * PSTR + 4]);
            #pragma unroll
            for (int j = 0; j < 8; j++) {
                float2 vv = *(const float2*)(VP + (j * 8 + grp) * VPSTR + kk * 8 + tig * 2);
                uint32_t bf[2] = { __float_as_uint(vv.x), __float_as_uint(vv.y) };
                mma_tf32(O[j], a, bf);
            }
        }

        __syncthreads();   // all warps done reading V buffer
        if (it + 1 < 16) { issueV(it + 1); CP_COMMIT(); }
    }

    // epilogue: normalize, round and write
    float inv0 = 1.f / l0, inv1 = 1.f / l1;
    float* ob = g_attn + ((size_t)b * CC + (size_t)h * 64) * NN + t0;
    int tr0 = w * 16 + grp, tr1 = tr0 + 8;
    #pragma unroll
    for (int j = 0; j < 8; j++) {
        int c0 = j * 8 + tig * 2;
        ob[(size_t)c0 * NN + tr0]       = totf(O[j][0] * inv0);
        ob[(size_t)(c0 + 1) * NN + tr0] = totf(O[j][1] * inv0);
        ob[(size_t)c0 * NN + tr1]       = totf(O[j][2] * inv1);
        ob[(size_t)(c0 + 1) * NN + tr1] = totf(O[j][3] * inv1);
    }
}

// ===========================================================================
// GroupNorm kernels
// ===========================================================================
__global__ void gn1_kernel(const float* __restrict__ x,
                           const float* __restrict__ sc,
                           const float* __restrict__ bi) {
    const int blk = blockIdx.x;
    const int b = blk / GG, g = blk % GG;
    const size_t base = ((size_t)b * CC + (size_t)g * CPG) * NN;
    const float* xp = x + base;
    const int tid = threadIdx.x;

    float s = 0.f, s2 = 0.f;
    for (int i = tid; i < CPG * NN; i += 256) {
        float v = xp[i];
        s += v; s2 += v * v;
    }
    __shared__ float r1[256], r2[256];
    r1[tid] = s; r2[tid] = s2;
    __syncthreads();
    for (int o = 128; o > 0; o >>= 1) {
        if (tid < o) { r1[tid] += r1[tid + o]; r2[tid] += r2[tid + o]; }
        __syncthreads();
    }
    __shared__ float mu_s, rstd_s;
    if (tid == 0) {
        float inv = 1.0f / (CPG * NN);
        float mu = r1[0] * inv;
        float var = r2[0] * inv - mu * mu;
        mu_s = mu; rstd_s = rsqrtf(var + EPSV);
    }
    __syncthreads();
    const float mu = mu_s, rstd = rstd_s;
    for (int i = tid; i < CPG * NN; i += 256) {
        int c = g * CPG + (i >> 10);
        g_hn[base + i] = totf((xp[i] - mu) * rstd * sc[c] + bi[c]);
    }
}

__global__ void gn2_res_kernel(const float* __restrict__ x,
                               const float* __restrict__ sc,
                               const float* __restrict__ bi,
                               float* __restrict__ out) {
    const int blk = blockIdx.x;
    const int b = blk / GG, g = blk % GG;
    const size_t base = ((size_t)b * CC + (size_t)g * CPG) * NN;
    const float* yp = g_proj + base;
    const int tid = threadIdx.x;

    float s = 0.f, s2 = 0.f;
    for (int i = tid; i < CPG * NN; i += 256) {
        float v = yp[i];
        s += v; s2 += v * v;
    }
    __shared__ float r1[256], r2[256];
    r1[tid] = s; r2[tid] = s2;
    __syncthreads();
    for (int o = 128; o > 0; o >>= 1) {
        if (tid < o) { r1[tid] += r1[tid + o]; r2[tid] += r2[tid + o]; }
        __syncthreads();
    }
    __shared__ float mu_s, rstd_s;
    if (tid == 0) {
        float inv = 1.0f / (CPG * NN);
        float mu = r1[0] * inv;
        float var = r2[0] * inv - mu * mu;
        mu_s = mu; rstd_s = rsqrtf(var + EPSV);
    }
    __syncthreads();
    const float mu = mu_s, rstd = rstd_s;
    for (int i = tid; i < CPG * NN; i += 256) {
        int c = g * CPG + (i >> 10);
        out[base + i] = x[base + i] + (yp[i] - mu) * rstd * sc[c] + bi[c];
    }
}

// ---------------------------------------------------------------------------
extern "C" void kernel_launch(void* const* d_in, const int* in_sizes, int n_in,
                              void* d_out, int out_size) {
    const float* x        = (const float*)d_in[0];
    const float* gn1_s    = (const float*)d_in[1];
    const float* gn1_b    = (const float*)d_in[2];
    const float* w_qkv    = (const float*)d_in[3];
    const float* b_qkv    = (const float*)d_in[4];
    const float* w_proj   = (const float*)d_in[5];
    const float* b_proj   = (const float*)d_in[6];
    const float* gn2_s    = (const float*)d_in[7];
    const float* gn2_b    = (const float*)d_in[8];
    float* out = (float*)d_out;

    const int FSMEM = SM_TOT * (int)sizeof(float);   // 53248 B
    cudaFuncSetAttribute(k_flash, cudaFuncAttributeMaxDynamicSharedMemorySize, FSMEM);
    cudaFuncSetAttribute(k_qkv,  cudaFuncAttributeMaxDynamicSharedMemorySize, GEMM_SMEM);
    cudaFuncSetAttribute(k_proj, cudaFuncAttributeMaxDynamicSharedMemorySize, GEMM_SMEM);

    // 0) round weights to tf32 (producer-side rounding)
    k_roundw<<<(3 * CC * CC + CC * CC) / 256, 256>>>(w_qkv, w_proj);
    // 1) GroupNorm1 (writes tf32-rounded hn)
    gn1_kernel<<<BB * GG, 256>>>(x, gn1_s, gn1_b);
    // 2) QKV GEMM; K/V routed to paired layouts in the epilogue
    k_qkv<<<dim3(8, 12, BB), 256, GEMM_SMEM>>>(b_qkv);
    // 3) Fused flash attention: 16 t-tiles x 64 bh, 128-thr blocks
    k_flash<<<dim3(16, 64), 128, FSMEM>>>();
    // 4) proj
    k_proj<<<dim3(8, 4, BB), 256, GEMM_SMEM>>>(b_proj);
    // 5) GroupNorm2 + residual
    gn2_res_kernel<<<BB * GG, 256>>>(x, gn2_s, gn2_b, out);
}